// round 1
// baseline (speedup 1.0000x reference)
#include <cuda_runtime.h>
#include <cuda_bf16.h>

// Problem: embeddings [B=512, I=128, D=64] fp32
// out[b,i,d] = tanh( emb[b,i,d] * (1/I) * sum_j emb[b,j,d] )
//
// One CTA per batch. 256 threads, each owns 8 float4 (32 floats) of the
// 128x64 tile held in REGISTERS -> input read from HBM exactly once.
// Per-thread column group c = t%16 is invariant across the 8 strided loads,
// so partial sums are d-aligned; 16x16 shared reduce -> mean[64].

static constexpr int BATCH   = 512;
static constexpr int SEQ_I   = 128;
static constexpr int DIM     = 64;
static constexpr int F4_PER_BATCH = SEQ_I * DIM / 4;  // 2048
static constexpr int THREADS = 256;
static constexpr int F4_PER_THREAD = F4_PER_BATCH / THREADS;  // 8

__device__ __forceinline__ float fast_tanh(float x) {
    float y;
    asm("tanh.approx.f32 %0, %1;" : "=f"(y) : "f"(x));
    return y;
}

__global__ __launch_bounds__(THREADS, 4)
void ATT0_40707700032104_kernel(const float4* __restrict__ in,
                                float4* __restrict__ out) {
    const int b = blockIdx.x;
    const int t = threadIdx.x;

    const float4* src = in  + (size_t)b * F4_PER_BATCH;
    float4*       dst = out + (size_t)b * F4_PER_BATCH;

    // ---- Load tile into registers, accumulate per-thread column partials ----
    float4 v[F4_PER_THREAD];
    float4 s = make_float4(0.f, 0.f, 0.f, 0.f);
#pragma unroll
    for (int k = 0; k < F4_PER_THREAD; k++) {
        v[k] = src[t + THREADS * k];
        s.x += v[k].x; s.y += v[k].y; s.z += v[k].z; s.w += v[k].w;
    }

    // ---- Cross-thread reduce: 16 row-groups per column group ----
    __shared__ float4 part[THREADS];
    __shared__ float4 mean4[16];
    part[t] = s;
    __syncthreads();

    if (t < 16) {
        // column group c = t; entries live at indices c + 16*r, r = 0..15
        float4 m = part[t];
#pragma unroll
        for (int r = 1; r < 16; r++) {
            float4 p = part[t + 16 * r];
            m.x += p.x; m.y += p.y; m.z += p.z; m.w += p.w;
        }
        const float inv = 1.0f / (float)SEQ_I;
        m.x *= inv; m.y *= inv; m.z *= inv; m.w *= inv;
        mean4[t] = m;
    }
    __syncthreads();

    const float4 m = mean4[t & 15];

    // ---- Apply: tanh(v * mean), straight from registers ----
#pragma unroll
    for (int k = 0; k < F4_PER_THREAD; k++) {
        float4 r;
        r.x = fast_tanh(v[k].x * m.x);
        r.y = fast_tanh(v[k].y * m.y);
        r.z = fast_tanh(v[k].z * m.z);
        r.w = fast_tanh(v[k].w * m.w);
        dst[t + THREADS * k] = r;
    }
}

extern "C" void kernel_launch(void* const* d_in, const int* in_sizes, int n_in,
                              void* d_out, int out_size) {
    const float4* in  = (const float4*)d_in[0];
    float4*       out = (float4*)d_out;
    ATT0_40707700032104_kernel<<<BATCH, THREADS>>>(in, out);
}

// round 2
// speedup vs baseline: 1.0037x; 1.0037x over previous
#include <cuda_runtime.h>
#include <cuda_bf16.h>

// embeddings [B=512, I=128, D=64] fp32
// out[b,i,d] = tanh( emb[b,i,d] * (1/I) * sum_j emb[b,j,d] )
//
// Column sums are independent per d -> split each batch's D across
// HALVES=2 CTAs. Grid = 1024 CTAs x 256 threads (~6.9 CTAs/SM) for deep
// in-flight load parallelism. Each CTA: 128 rows x 8 float4 (32 floats).
// Thread t owns f4-column c=t&7, row-group r=t>>3; 4 strided row loads
// held in registers (input read from HBM exactly once). Warp shuffle
// (xor 8,16) + 8x8 smem stage -> mean[8 float4], then tanh+store.

static constexpr int BATCH   = 512;
static constexpr int SEQ_I   = 128;
static constexpr int DIM     = 64;
static constexpr int HALVES  = 2;
static constexpr int F4_ROW  = DIM / 4;            // 16 f4 per full row
static constexpr int F4_COLS = F4_ROW / HALVES;    // 8 f4 columns per CTA
static constexpr int THREADS = 256;
static constexpr int ROWGRPS = THREADS / F4_COLS;  // 32
static constexpr int ROWS_PT = SEQ_I / ROWGRPS;    // 4 rows per thread

__device__ __forceinline__ float fast_tanh(float x) {
    float y;
    asm("tanh.approx.f32 %0, %1;" : "=f"(y) : "f"(x));
    return y;
}

__global__ __launch_bounds__(THREADS, 8)
void ATT0_40707700032104_kernel(const float4* __restrict__ in,
                                float4* __restrict__ out) {
    const int b    = blockIdx.x >> 1;          // batch
    const int half = blockIdx.x & 1;           // which 32-float D-chunk
    const int t    = threadIdx.x;
    const int c    = t & (F4_COLS - 1);        // f4 column within chunk (0..7)
    const int rg   = t >> 3;                   // row group (0..31)
    const int lane = t & 31;
    const int w    = t >> 5;                   // warp id (0..7)

    const size_t base = (size_t)b * (SEQ_I * F4_ROW) + half * F4_COLS + c;
    const float4* src = in  + base;
    float4*       dst = out + base;

    // ---- Load 4 rows into registers, accumulate per-column partial ----
    float4 v[ROWS_PT];
    float4 s = make_float4(0.f, 0.f, 0.f, 0.f);
#pragma unroll
    for (int k = 0; k < ROWS_PT; k++) {
        v[k] = src[(size_t)(rg + ROWGRPS * k) * F4_ROW];
        s.x += v[k].x; s.y += v[k].y; s.z += v[k].z; s.w += v[k].w;
    }

    // ---- Warp reduce: lanes l, l+8, l+16, l+24 share column c ----
#pragma unroll
    for (int off = 8; off <= 16; off <<= 1) {
        s.x += __shfl_xor_sync(0xffffffffu, s.x, off);
        s.y += __shfl_xor_sync(0xffffffffu, s.y, off);
        s.z += __shfl_xor_sync(0xffffffffu, s.z, off);
        s.w += __shfl_xor_sync(0xffffffffu, s.w, off);
    }

    // ---- Cross-warp reduce via 8x8 smem stage ----
    __shared__ float4 wsum[8][F4_COLS];
    __shared__ float4 mean4[F4_COLS];
    if (lane < F4_COLS) wsum[w][lane] = s;
    __syncthreads();

    if (t < F4_COLS) {
        float4 m = wsum[0][t];
#pragma unroll
        for (int ww = 1; ww < 8; ww++) {
            float4 p = wsum[ww][t];
            m.x += p.x; m.y += p.y; m.z += p.z; m.w += p.w;
        }
        const float inv = 1.0f / (float)SEQ_I;
        m.x *= inv; m.y *= inv; m.z *= inv; m.w *= inv;
        mean4[t] = m;
    }
    __syncthreads();

    const float4 m = mean4[c];

    // ---- Apply tanh(v * mean) from registers, store ----
#pragma unroll
    for (int k = 0; k < ROWS_PT; k++) {
        float4 r;
        r.x = fast_tanh(v[k].x * m.x);
        r.y = fast_tanh(v[k].y * m.y);
        r.z = fast_tanh(v[k].z * m.z);
        r.w = fast_tanh(v[k].w * m.w);
        dst[(size_t)(rg + ROWGRPS * k) * F4_ROW] = r;
    }
}

extern "C" void kernel_launch(void* const* d_in, const int* in_sizes, int n_in,
                              void* d_out, int out_size) {
    const float4* in  = (const float4*)d_in[0];
    float4*       out = (float4*)d_out;
    ATT0_40707700032104_kernel<<<BATCH * HALVES, THREADS>>>(in, out);
}